// round 8
// baseline (speedup 1.0000x reference)
#include <cuda_runtime.h>
#include <stdint.h>

#define BATCH   32768
#define NTREE   256
#define NNODE   2047
#define NFEAT   256
#define NCLS    8
#define DEPTH   10
#define SCHUNK  128
#define THREADS 512           // 128 samples x 4 tree-lanes (1 chain each)
#define GTREES  4
#define NCHUNK  (BATCH / SCHUNK)          // 256
#define NGROUPS (NTREE / GTREES)          // 64
#define NITEMS  (NCHUNK * NGROUPS)        // 16384, chunk-major
#define NSM     148
#define NSLOT   1024          // 8KB slab per tree (1023 internal nodes used)
#define GRPBYTES (GTREES * NSLOT * 8)     // 32768

// smem map: [0,128K) x | [128K,+32K)x2 node bufs | idx x2 | mbars
#define SM_X      0
#define SM_NODES  131072
#define SM_IDX    196608
#define IDX_PITCH 5
#define IDX_BYTES (SCHUNK * IDX_PITCH * 4)   // 2560
#define SM_MBAR   (SM_IDX + 2 * IDX_BYTES)   // 201728
#define SM_TOTAL  (SM_MBAR + 16)

__device__ uint2 g_nodes2[NTREE * NSLOT];   // internal nodes: {thr bits, feat*512}
__device__ float g_xT[NFEAT * BATCH];       // x transposed [feature][sample]

// ---------------- merged prep: transpose x + pack nodes ----------------
__global__ void prep_k(const float* __restrict__ x,
                       const int* __restrict__ features,
                       const float* __restrict__ thresholds) {
    int b = blockIdx.x;
    const int TBLK = (NFEAT / 32) * (BATCH / 32);
    if (b < TBLK) {
        __shared__ float tile[32][33];
        int f0 = (b & 7) * 32, s0 = (b >> 3) * 32;
        int lx = threadIdx.x & 31, ly = threadIdx.x >> 5;   // 256 threads
        #pragma unroll
        for (int k = ly; k < 32; k += 8)
            tile[k][lx] = x[(size_t)(s0 + k) * NFEAT + f0 + lx];
        __syncthreads();
        #pragma unroll
        for (int k = ly; k < 32; k += 8)
            g_xT[(size_t)(f0 + k) * BATCH + s0 + lx] = tile[lx][k];
    } else {
        int i = (b - TBLK) * 256 + threadIdx.x;
        if (i < NTREE * 1023) {
            int t = i / 1023;
            int n = i - t * 1023;
            int src = t * NNODE + n;
            uint2 v;
            v.x = __float_as_uint(thresholds[src]);
            v.y = (unsigned)features[src] * (SCHUNK * 4);
            g_nodes2[t * NSLOT + n] = v;
        }
    }
}

// ---------------- helpers ----------------
__device__ __forceinline__ void stage_x(char* sm, int s0, int tid) {
    float4* xs4 = (float4*)(sm + SM_X);
    #pragma unroll
    for (int j = 0; j < 16; j++) {
        int i4 = tid + THREADS * j;                 // 8192 float4
        int f = i4 >> 5, o = i4 & 31;
        xs4[i4] = *(const float4*)(g_xT + (size_t)f * BATCH + s0 + o * 4);
    }
}

__device__ __forceinline__ void bulk_fetch_nodes(unsigned dst, int g, unsigned mbar) {
    // one-shot 32KB DMA (caller: single thread)
    asm volatile("mbarrier.arrive.expect_tx.shared.b64 _, [%0], %1;"
                 :: "r"(mbar), "r"((unsigned)GRPBYTES) : "memory");
    const char* src = (const char*)g_nodes2 + (size_t)g * GRPBYTES;
    asm volatile("cp.async.bulk.shared::cta.global.mbarrier::complete_tx::bytes "
                 "[%0], [%1], %2, [%3];"
                 :: "r"(dst), "l"(src), "r"((unsigned)GRPBYTES), "r"(mbar) : "memory");
}

__device__ __forceinline__ void mbar_wait(unsigned mbar, unsigned parity) {
    unsigned done;
    asm volatile("{\n\t.reg .pred p;\n\t"
                 "mbarrier.try_wait.parity.acquire.cta.shared::cta.b64 p, [%1], %2;\n\t"
                 "selp.b32 %0, 1, 0, p;\n\t}"
                 : "=r"(done) : "r"(mbar), "r"(parity) : "memory");
    if (!done) {
        asm volatile("{\n\t.reg .pred P1;\n\t"
                     "W%=:\n\t"
                     "mbarrier.try_wait.parity.acquire.cta.shared::cta.b64 P1, [%0], %1, 0x989680;\n\t"
                     "@P1 bra.uni D%=;\n\t"
                     "bra.uni W%=;\n\t"
                     "D%=:\n\t}"
                     :: "r"(mbar), "r"(parity) : "memory");
    }
}

// ---------------- main traversal (persistent, double-buffered nodes) ----------------
__global__ __launch_bounds__(THREADS, 1)
void traverse_k(const float* __restrict__ values, float* __restrict__ out) {
    extern __shared__ char sm[];
    int tid = threadIdx.x;

    unsigned smbase;
    asm("{ .reg .u64 t; cvta.to.shared.u64 t, %1; cvt.u32.u64 %0, t; }"
        : "=r"(smbase) : "l"(sm));

    int istart = (int)((long long)blockIdx.x * NITEMS / NSM);
    int iend   = (int)((long long)(blockIdx.x + 1) * NITEMS / NSM);

    int sl = tid & (SCHUNK - 1);
    int tl = tid >> 7;                         // 0..3: tree within group
    unsigned xaddr = smbase + SM_X + sl * 4;

    // prologue: init mbars, launch DMAs for first two items, stage x
    if (tid == 0) {
        asm volatile("mbarrier.init.shared.b64 [%0], 1;" :: "r"(smbase + SM_MBAR) : "memory");
        asm volatile("mbarrier.init.shared.b64 [%0], 1;" :: "r"(smbase + SM_MBAR + 8) : "memory");
    }
    __syncthreads();
    if (tid == 0) {
        bulk_fetch_nodes(smbase + SM_NODES, istart & (NGROUPS - 1), smbase + SM_MBAR);
        if (istart + 1 < iend)
            bulk_fetch_nodes(smbase + SM_NODES + GRPBYTES,
                             (istart + 1) & (NGROUPS - 1), smbase + SM_MBAR + 8);
    }
    int cur_chunk = istart >> 6;
    stage_x(sm, cur_chunk * SCHUNK, tid);
    __syncthreads();                            // x visible

    float4 vreg[2];
    float* prev_obase = out;

    for (int i = istart; i < iend; i++) {
        int k = i - istart;
        int buf = k & 1;
        int chunk = i >> 6;
        int g = i & (NGROUPS - 1);
        int s0 = chunk * SCHUNK;
        int t0 = g * GTREES;

        if (chunk != cur_chunk) {               // all threads past prev end barrier
            stage_x(sm, s0, tid);
            cur_chunk = chunk;
            __syncthreads();
        }

        // issue prev item's values gather (long-latency LDGs first)
        if (i > istart) {
            const unsigned* rb = (const unsigned*)(sm + SM_IDX + ((i - 1) & 1) * IDX_BYTES);
            #pragma unroll
            for (int j = 0; j < 2; j++) {
                int e = tid + THREADS * j;      // 0..1023
                int sl2 = e >> 3, tg = (e >> 1) & 3, half = e & 1;
                unsigned vrow = rb[sl2 * IDX_PITCH + tg];
                vreg[j] = __ldg((const float4*)values + (size_t)vrow * 2 + half);
            }
        }

        mbar_wait(smbase + SM_MBAR + 8 * buf, (unsigned)((k >> 1) & 1));   // nodes[i] ready

        // ---- traversal: 1 chain, all loads from shared
        unsigned base = smbase + SM_NODES + buf * GRPBYTES + tl * (NSLOT * 8);
        unsigned c = 8u - base;
        unsigned o = base;
        #pragma unroll
        for (int d = 0; d < DEPTH; d++) {
            unsigned ax, ay;
            asm("ld.shared.v2.u32 {%0,%1}, [%2];" : "=r"(ax), "=r"(ay) : "r"(o));
            float fa;
            asm("ld.shared.f32 %0, [%1];" : "=f"(fa) : "r"(xaddr + ay));
            o = o * 2u + c + ((fa >= __uint_as_float(ax)) ? 8u : 0u);
        }
        unsigned leaf = (o - base) >> 3;        // 1023..2046

        // ---- store prev item's gathered values (coalesced)
        if (i > istart) {
            #pragma unroll
            for (int j = 0; j < 2; j++) {
                int e = tid + THREADS * j;
                int sl2 = e >> 3, tg = (e >> 1) & 3, half = e & 1;
                *(float4*)(prev_obase + (size_t)sl2 * (NTREE * NCLS) + tg * NCLS + half * 4) = vreg[j];
            }
        }

        // ---- publish this item's values-row indices (pitch 5, conflict-free)
        {
            unsigned* wb = (unsigned*)(sm + SM_IDX + (i & 1) * IDX_BYTES);
            wb[sl * IDX_PITCH + tl] = (unsigned)(t0 + tl) * NNODE + leaf;
        }
        __syncthreads();                        // idx visible; node reads of buf done

        // refill the buffer just vacated (for item i+2) — a full item of lead time
        if (i + 2 < iend && tid == 0)
            bulk_fetch_nodes(smbase + SM_NODES + buf * GRPBYTES,
                             (i + 2) & (NGROUPS - 1), smbase + SM_MBAR + 8 * buf);

        prev_obase = out + (size_t)s0 * (NTREE * NCLS) + t0 * NCLS;
    }

    // epilogue: gather + store for the last item
    {
        const unsigned* rb = (const unsigned*)(sm + SM_IDX + ((iend - 1) & 1) * IDX_BYTES);
        #pragma unroll
        for (int j = 0; j < 2; j++) {
            int e = tid + THREADS * j;
            int sl2 = e >> 3, tg = (e >> 1) & 3, half = e & 1;
            unsigned vrow = rb[sl2 * IDX_PITCH + tg];
            vreg[j] = __ldg((const float4*)values + (size_t)vrow * 2 + half);
        }
        #pragma unroll
        for (int j = 0; j < 2; j++) {
            int e = tid + THREADS * j;
            int sl2 = e >> 3, tg = (e >> 1) & 3, half = e & 1;
            *(float4*)(prev_obase + (size_t)sl2 * (NTREE * NCLS) + tg * NCLS + half * 4) = vreg[j];
        }
    }
}

extern "C" void kernel_launch(void* const* d_in, const int* in_sizes, int n_in,
                              void* d_out, int out_size) {
    // metadata order: x, lefts, rights, features, thresholds, values, nodes_offset
    const float* x          = (const float*)d_in[0];
    const int*   features   = (const int*)  d_in[3];
    const float* thresholds = (const float*)d_in[4];
    const float* values     = (const float*)d_in[5];

    cudaFuncSetAttribute(traverse_k, cudaFuncAttributeMaxDynamicSharedMemorySize, SM_TOTAL);

    int prep_blocks = (NFEAT / 32) * (BATCH / 32) + (NTREE * 1023 + 255) / 256;
    prep_k<<<prep_blocks, 256>>>(x, features, thresholds);
    traverse_k<<<NSM, THREADS, SM_TOTAL>>>(values, (float*)d_out);
}